// round 14
// baseline (speedup 1.0000x reference)
#include <cuda_runtime.h>
#include <cuda_fp16.h>
#include <cstdint>

// Problem constants
#define D_MODEL 768
#define D_INNER 768
#define D_STATE 8
#define BATCH   4
#define SEQ     8192
#define M_TOT   (BATCH * SEQ)        // 32768
#define N_IN    (2 * D_INNER)        // 1536
#define KDIM    768
#define CHUNK   32
#define NCHUNK  (SEQ / CHUNK)        // 256

// Scratch (static __device__ arrays per allocation rules)
__device__ __half g_Xh[(size_t)M_TOT * D_MODEL];         // fp16 x
__device__ float  g_XZ[(size_t)M_TOT * N_IN];            // x @ W_in (fp32)
__device__ __half g_YZh[(size_t)M_TOT * D_INNER];        // fp16 y*silu(z)
__device__ __half g_Wh[(size_t)KDIM * N_IN + (size_t)KDIM * D_MODEL]; // fp16 W_in | W_out
__device__ float  g_CS[(size_t)BATCH * NCHUNK * D_INNER]; // chunk sums / offsets

// ---------------------------------------------------------------------------
// fp32 -> fp16 conversion (used for x and both weights)
// ---------------------------------------------------------------------------
__global__ __launch_bounds__(256) void convert_h_kernel(
    const float* __restrict__ in, __half* __restrict__ out, int n4)
{
    int i = blockIdx.x * blockDim.x + threadIdx.x;
    if (i >= n4) return;
    float4 v = ((const float4*)in)[i];
    __half2 h0 = __floats2half2_rn(v.x, v.y);
    __half2 h1 = __floats2half2_rn(v.z, v.w);
    ((uint2*)out)[i] = make_uint2(*(uint32_t*)&h0, *(uint32_t*)&h1);
}

// ---------------------------------------------------------------------------
// FP16 tensor-core GEMM: 128x128 blocktile, BK=32, 3-stage cp.async ring,
// ldmatrix fragment loads. 128 threads = 4 warps (2m x 2n); warp tile 64x64;
// mma.m16n8k16.f16 with fp32 accumulate. 0.25 LDSM per MMA.
// A: half row-major [M,K]. Bh: half row-major [K,N]. C: fp32 [M,N].
// ---------------------------------------------------------------------------
#define BM 128
#define BN 128
#define BKT 32
#define STAGES 3
#define AH_STRIDE 40                        // 32 + 8 pad halfs (80B rows)
#define BH_STRIDE 136                       // 128 + 8 pad halfs (272B rows)
#define A_STAGE_H (BM * AH_STRIDE)          // 5120 halfs = 10240 B
#define B_STAGE_H (BKT * BH_STRIDE)         // 4352 halfs = 8704 B
#define GEMM_SMEM_BYTES (STAGES * (A_STAGE_H + B_STAGE_H) * 2)  // 56832

__device__ __forceinline__ void mma_fp16(float* d, const uint32_t* a, const uint32_t* b) {
    asm volatile(
        "mma.sync.aligned.m16n8k16.row.col.f32.f16.f16.f32 "
        "{%0,%1,%2,%3}, {%4,%5,%6,%7}, {%8,%9}, {%0,%1,%2,%3};\n"
        : "+f"(d[0]), "+f"(d[1]), "+f"(d[2]), "+f"(d[3])
        : "r"(a[0]), "r"(a[1]), "r"(a[2]), "r"(a[3]), "r"(b[0]), "r"(b[1]));
}

__device__ __forceinline__ void ldsm_x4(uint32_t* r, uint32_t addr) {
    asm volatile("ldmatrix.sync.aligned.m8n8.x4.shared.b16 {%0,%1,%2,%3}, [%4];"
                 : "=r"(r[0]), "=r"(r[1]), "=r"(r[2]), "=r"(r[3]) : "r"(addr));
}
__device__ __forceinline__ void ldsm_x4_t(uint32_t* r, uint32_t addr) {
    asm volatile("ldmatrix.sync.aligned.m8n8.x4.trans.shared.b16 {%0,%1,%2,%3}, [%4];"
                 : "=r"(r[0]), "=r"(r[1]), "=r"(r[2]), "=r"(r[3]) : "r"(addr));
}

__device__ __forceinline__ void cpa16(void* dst, const void* src) {
    unsigned d = (unsigned)__cvta_generic_to_shared(dst);
    asm volatile("cp.async.cg.shared.global [%0], [%1], 16;" :: "r"(d), "l"(src) : "memory");
}

__global__ __launch_bounds__(128, 3) void gemm_fp16_kernel(
    const __half* __restrict__ A, const __half* __restrict__ Bh,
    float* __restrict__ C, int M, int N, int K)
{
    extern __shared__ char smem[];
    __half* Asm = (__half*)smem;                            // [STAGES][BM][AH_STRIDE]
    __half* Bsm = (__half*)(smem + STAGES * A_STAGE_H * 2); // [STAGES][BKT][BH_STRIDE]

    const int tid  = threadIdx.x;
    const int lane = tid & 31;
    const int wid  = tid >> 5;
    const int wm   = wid >> 1;   // 0..1 -> m offset 64*wm
    const int wn   = wid & 1;    // 0..1 -> n offset 64*wn
    const int bm   = blockIdx.y;
    const int bn   = blockIdx.x;

    const __half* Ab = A + (size_t)bm * BM * K;
    const __half* Bb = Bh + (size_t)bn * BN;

    float acc[4][8][4];
    #pragma unroll
    for (int mi = 0; mi < 4; mi++)
        #pragma unroll
        for (int ni = 0; ni < 8; ni++)
            #pragma unroll
            for (int q = 0; q < 4; q++) acc[mi][ni][q] = 0.0f;

    const int NT = K / BKT;   // 24

    auto load_stage = [&](int kt, int st) {
        __half* As = Asm + st * A_STAGE_H;
        __half* Bs = Bsm + st * B_STAGE_H;
        const int k0 = kt * BKT;
        // A tile 128x32 halfs = 512 x 16B, 4 per thread
        #pragma unroll
        for (int i = 0; i < 4; i++) {
            const int idx = tid + i * 128;
            const int r = idx >> 2, c8 = (idx & 3) << 3;
            cpa16(&As[r * AH_STRIDE + c8], Ab + (size_t)r * K + k0 + c8);
        }
        // B tile 32x128 halfs = 512 x 16B, 4 per thread
        #pragma unroll
        for (int i = 0; i < 4; i++) {
            const int idx = tid + i * 128;
            const int r = idx >> 4, c8 = (idx & 15) << 3;
            cpa16(&Bs[r * BH_STRIDE + c8], Bb + (size_t)(k0 + r) * N + c8);
        }
        asm volatile("cp.async.commit_group;" ::: "memory");
    };

    // ldmatrix per-lane base offsets (bytes)
    const uint32_t asm_u32 = (uint32_t)__cvta_generic_to_shared(Asm);
    const uint32_t bsm_u32 = (uint32_t)__cvta_generic_to_shared(Bsm);
    const uint32_t a_lane = ((wm * 64 + (lane & 15)) * AH_STRIDE + (lane >> 4) * 8) * 2;
    const uint32_t b_lane = (((((lane >> 3) & 1) * 8) + (lane & 7)) * BH_STRIDE
                             + wn * 64 + (lane >> 4) * 8) * 2;

    load_stage(0, 0);
    load_stage(1, 1);

    for (int kt = 0; kt < NT; kt++) {
        if (kt + 2 < NT) {
            asm volatile("cp.async.wait_group 1;" ::: "memory");
        } else {
            asm volatile("cp.async.wait_group 0;" ::: "memory");
        }
        __syncthreads();

        if (kt + 2 < NT) load_stage(kt + 2, (kt + 2) % STAGES);

        const int st = kt % STAGES;
        const uint32_t a_st = asm_u32 + st * A_STAGE_H * 2 + a_lane;
        const uint32_t b_st = bsm_u32 + st * B_STAGE_H * 2 + b_lane;

        #pragma unroll
        for (int ks2 = 0; ks2 < 2; ks2++) {       // two k16 steps per BKT=32
            uint32_t afr[4][4];
            const uint32_t aa = a_st + ks2 * 32;  // +16 halfs
            #pragma unroll
            for (int mi = 0; mi < 4; mi++)
                ldsm_x4(afr[mi], aa + mi * 16 * AH_STRIDE * 2);

            uint32_t bfr[8][2];
            #pragma unroll
            for (int ni2 = 0; ni2 < 4; ni2++) {   // 2 n8-groups per LDSM
                uint32_t r[4];
                ldsm_x4_t(r, b_st + ks2 * 16 * BH_STRIDE * 2 + ni2 * 32);
                bfr[2 * ni2][0] = r[0]; bfr[2 * ni2][1] = r[1];
                bfr[2 * ni2 + 1][0] = r[2]; bfr[2 * ni2 + 1][1] = r[3];
            }
            #pragma unroll
            for (int mi = 0; mi < 4; mi++)
                #pragma unroll
                for (int ni = 0; ni < 8; ni++)
                    mma_fp16(acc[mi][ni], afr[mi], bfr[ni]);
        }
    }

    float* Cb = C + (size_t)bm * BM * N + (size_t)bn * BN;
    #pragma unroll
    for (int mi = 0; mi < 4; mi++) {
        #pragma unroll
        for (int ni = 0; ni < 8; ni++) {
            const int r = wm * 64 + mi * 16 + (lane >> 2);
            const int c = wn * 64 + ni * 8 + ((lane & 3) << 1);
            *(float2*)&Cb[(size_t)r * N + c] =
                make_float2(acc[mi][ni][0], acc[mi][ni][1]);
            *(float2*)&Cb[(size_t)(r + 8) * N + c] =
                make_float2(acc[mi][ni][2], acc[mi][ni][3]);
        }
    }
}

// ---------------------------------------------------------------------------
// silu helper
// ---------------------------------------------------------------------------
__device__ __forceinline__ float silu_f(float v) {
    return v / (1.0f + __expf(-v));
}

// ---------------------------------------------------------------------------
// Pass A: per-chunk sums of u = silu(conv3(xc)+bias). 4 channels per thread.
// ---------------------------------------------------------------------------
__global__ __launch_bounds__(192) void scan_partial_kernel(
    const float* __restrict__ xz,
    const float* __restrict__ convw, const float* __restrict__ convb,
    float* __restrict__ csum)
{
    const int tq = threadIdx.x;
    const int chunk = blockIdx.x;
    const int b = blockIdx.y;
    const int t0 = chunk * CHUNK;
    const int c0 = tq * 4;

    float w0[4], w1[4], w2[4], cb[4];
    #pragma unroll
    for (int j = 0; j < 4; j++) {
        w0[j] = convw[(c0 + j) * 3 + 0];
        w1[j] = convw[(c0 + j) * 3 + 1];
        w2[j] = convw[(c0 + j) * 3 + 2];
        cb[j] = convb[c0 + j];
    }

    const float* p = xz + ((size_t)b * SEQ + t0) * N_IN + c0;

    float4 xm2 = make_float4(0, 0, 0, 0), xm1 = make_float4(0, 0, 0, 0);
    if (t0 >= 2) {
        xm2 = *(const float4*)(p - 2 * N_IN);
        xm1 = *(const float4*)(p - 1 * N_IN);
    }

    float s[4] = {0, 0, 0, 0};
    #pragma unroll 8
    for (int t = 0; t < CHUNK; t++) {
        float4 x0 = *(const float4*)(p + (size_t)t * N_IN);
        float m2[4] = {xm2.x, xm2.y, xm2.z, xm2.w};
        float m1[4] = {xm1.x, xm1.y, xm1.z, xm1.w};
        float cc[4] = {x0.x, x0.y, x0.z, x0.w};
        #pragma unroll
        for (int j = 0; j < 4; j++) {
            float v = fmaf(w0[j], m2[j], fmaf(w1[j], m1[j], fmaf(w2[j], cc[j], cb[j])));
            s[j] += silu_f(v);
        }
        xm2 = xm1; xm1 = x0;
    }
    *(float4*)&csum[((size_t)b * NCHUNK + chunk) * D_INNER + c0] =
        make_float4(s[0], s[1], s[2], s[3]);
}

// ---------------------------------------------------------------------------
// Pass B: block-parallel exclusive scan over NCHUNK chunk sums.
// ---------------------------------------------------------------------------
__global__ __launch_bounds__(NCHUNK) void scan_offsets_kernel(float* __restrict__ csum)
{
    __shared__ float4 sh[NCHUNK];
    const int k = threadIdx.x;
    const int c0 = blockIdx.x * 4;
    const int b = blockIdx.y;

    float4* ptr = (float4*)&csum[((size_t)b * NCHUNK + k) * D_INNER + c0];
    float4 v = *ptr;
    sh[k] = v;
    __syncthreads();

    #pragma unroll
    for (int off = 1; off < NCHUNK; off <<= 1) {
        float4 t = make_float4(0, 0, 0, 0);
        const bool has = (k >= off);
        if (has) t = sh[k - off];
        __syncthreads();
        if (has) {
            v.x += t.x; v.y += t.y; v.z += t.z; v.w += t.w;
            sh[k] = v;
        }
        __syncthreads();
    }
    float4 ex = (k > 0) ? sh[k - 1] : make_float4(0, 0, 0, 0);
    *ptr = ex;
}

// ---------------------------------------------------------------------------
// Pass C: recompute u, y = cum*BC + u*D, times silu(z); write fp16 yz.
// ---------------------------------------------------------------------------
__global__ __launch_bounds__(192) void scan_apply_kernel(
    const float* __restrict__ xz,
    const float* __restrict__ convw, const float* __restrict__ convb,
    const float* __restrict__ Bm, const float* __restrict__ Cm,
    const float* __restrict__ Dv,
    const float* __restrict__ csum,
    __half* __restrict__ yz)
{
    const int tq = threadIdx.x;
    const int chunk = blockIdx.x;
    const int b = blockIdx.y;
    const int t0 = chunk * CHUNK;
    const int c0 = tq * 4;

    float w0[4], w1[4], w2[4], cb[4], bc[4], dd[4];
    #pragma unroll
    for (int j = 0; j < 4; j++) {
        w0[j] = convw[(c0 + j) * 3 + 0];
        w1[j] = convw[(c0 + j) * 3 + 1];
        w2[j] = convw[(c0 + j) * 3 + 2];
        cb[j] = convb[c0 + j];
        float acc = 0.0f;
        #pragma unroll
        for (int s = 0; s < D_STATE; s++)
            acc = fmaf(Bm[(c0 + j) * D_STATE + s], Cm[(c0 + j) * D_STATE + s], acc);
        bc[j] = acc;
        dd[j] = Dv[c0 + j];
    }

    const float* p = xz + ((size_t)b * SEQ + t0) * N_IN + c0;
    __half* q = yz + ((size_t)b * SEQ + t0) * D_INNER + c0;

    float4 xm2 = make_float4(0, 0, 0, 0), xm1 = make_float4(0, 0, 0, 0);
    if (t0 >= 2) {
        xm2 = *(const float4*)(p - 2 * N_IN);
        xm1 = *(const float4*)(p - 1 * N_IN);
    }

    float4 runv = *(const float4*)&csum[((size_t)b * NCHUNK + chunk) * D_INNER + c0];
    float run[4] = {runv.x, runv.y, runv.z, runv.w};

    #pragma unroll 8
    for (int t = 0; t < CHUNK; t++) {
        float4 x0 = *(const float4*)(p + (size_t)t * N_IN);
        float4 zz = *(const float4*)(p + (size_t)t * N_IN + D_INNER);
        float m2[4] = {xm2.x, xm2.y, xm2.z, xm2.w};
        float m1[4] = {xm1.x, xm1.y, xm1.z, xm1.w};
        float cc[4] = {x0.x, x0.y, x0.z, x0.w};
        float zv[4] = {zz.x, zz.y, zz.z, zz.w};
        float o[4];
        #pragma unroll
        for (int j = 0; j < 4; j++) {
            float v = fmaf(w0[j], m2[j], fmaf(w1[j], m1[j], fmaf(w2[j], cc[j], cb[j])));
            float u = silu_f(v);
            run[j] += u;
            float y = fmaf(run[j], bc[j], u * dd[j]);
            o[j] = y * silu_f(zv[j]);
        }
        __half2 h01 = __floats2half2_rn(o[0], o[1]);
        __half2 h23 = __floats2half2_rn(o[2], o[3]);
        *(uint2*)(q + (size_t)t * D_INNER) =
            make_uint2(*(uint32_t*)&h01, *(uint32_t*)&h23);
        xm2 = xm1; xm1 = x0;
    }
}

// ---------------------------------------------------------------------------
// Launch
// ---------------------------------------------------------------------------
extern "C" void kernel_launch(void* const* d_in, const int* in_sizes, int n_in,
                              void* d_out, int out_size)
{
    const float* x      = (const float*)d_in[0];
    const float* W_in   = (const float*)d_in[1];
    const float* conv_w = (const float*)d_in[2];
    const float* conv_b = (const float*)d_in[3];
    const float* Bm     = (const float*)d_in[4];
    const float* Cm     = (const float*)d_in[5];
    const float* Dv     = (const float*)d_in[6];
    const float* W_out  = (const float*)d_in[7];
    float* out = (float*)d_out;

    __half* xh;  cudaGetSymbolAddress((void**)&xh, g_Xh);
    float*  xz;  cudaGetSymbolAddress((void**)&xz, g_XZ);
    __half* yzh; cudaGetSymbolAddress((void**)&yzh, g_YZh);
    __half* wh;  cudaGetSymbolAddress((void**)&wh, g_Wh);
    float*  cs;  cudaGetSymbolAddress((void**)&cs, g_CS);

    __half* wh_in  = wh;                             // [768][1536]
    __half* wh_out = wh + (size_t)KDIM * N_IN;       // [768][768]

    static bool attr_done = false;
    if (!attr_done) {
        cudaFuncSetAttribute(gemm_fp16_kernel,
                             cudaFuncAttributeMaxDynamicSharedMemorySize, GEMM_SMEM_BYTES);
        attr_done = true;
    }

    // Preprocessing: x and weights -> fp16
    {
        int n4 = (M_TOT * D_MODEL) / 4;
        convert_h_kernel<<<(n4 + 255) / 256, 256>>>(x, xh, n4);
        n4 = (KDIM * N_IN) / 4;
        convert_h_kernel<<<(n4 + 255) / 256, 256>>>(W_in, wh_in, n4);
        n4 = (KDIM * D_MODEL) / 4;
        convert_h_kernel<<<(n4 + 255) / 256, 256>>>(W_out, wh_out, n4);
    }

    // GEMM1: xz = xh @ W_in   [32768,768] x [768,1536]
    {
        dim3 grid(N_IN / BN, M_TOT / BM);
        gemm_fp16_kernel<<<grid, 128, GEMM_SMEM_BYTES>>>(
            xh, wh_in, xz, M_TOT, N_IN, KDIM);
    }
    // Scan pipeline
    {
        dim3 grid(NCHUNK, BATCH);
        scan_partial_kernel<<<grid, 192>>>(xz, conv_w, conv_b, cs);
        scan_offsets_kernel<<<dim3(D_INNER / 4, BATCH), NCHUNK>>>(cs);
        scan_apply_kernel<<<grid, 192>>>(xz, conv_w, conv_b, Bm, Cm, Dv, cs, yzh);
    }
    // GEMM2: out = yzh @ W_out  [32768,768] x [768,768]
    {
        dim3 grid(D_MODEL / BN, M_TOT / BM);
        gemm_fp16_kernel<<<grid, 128, GEMM_SMEM_BYTES>>>(
            yzh, wh_out, out, M_TOT, D_MODEL, KDIM);
    }
}

// round 15
// speedup vs baseline: 1.0260x; 1.0260x over previous
#include <cuda_runtime.h>
#include <cuda_fp16.h>
#include <cstdint>

// Problem constants
#define D_MODEL 768
#define D_INNER 768
#define D_STATE 8
#define BATCH   4
#define SEQ     8192
#define M_TOT   (BATCH * SEQ)        // 32768
#define N_IN    (2 * D_INNER)        // 1536
#define KDIM    768
#define CHUNK   32
#define NCHUNK  (SEQ / CHUNK)        // 256

// Scratch (static __device__ arrays per allocation rules)
__device__ __half g_Xh[(size_t)M_TOT * D_MODEL];         // fp16 x
__device__ float  g_XC[(size_t)M_TOT * D_INNER];         // xc (fp32, pre-conv)
__device__ __half g_ZS[(size_t)M_TOT * D_INNER];         // silu(z) fp16
__device__ __half g_YZh[(size_t)M_TOT * D_INNER];        // fp16 y*silu(z)
__device__ __half g_Wh[(size_t)KDIM * N_IN + (size_t)KDIM * D_MODEL]; // fp16 W_in | W_out
__device__ float  g_CS[(size_t)BATCH * NCHUNK * D_INNER]; // chunk sums / offsets

// ---------------------------------------------------------------------------
// silu helper
// ---------------------------------------------------------------------------
__device__ __forceinline__ float silu_f(float v) {
    return v / (1.0f + __expf(-v));
}

// ---------------------------------------------------------------------------
// fp32 -> fp16 conversion (used for x and both weights)
// ---------------------------------------------------------------------------
__global__ __launch_bounds__(256) void convert_h_kernel(
    const float* __restrict__ in, __half* __restrict__ out, int n4)
{
    int i = blockIdx.x * blockDim.x + threadIdx.x;
    if (i >= n4) return;
    float4 v = ((const float4*)in)[i];
    __half2 h0 = __floats2half2_rn(v.x, v.y);
    __half2 h1 = __floats2half2_rn(v.z, v.w);
    ((uint2*)out)[i] = make_uint2(*(uint32_t*)&h0, *(uint32_t*)&h1);
}

// ---------------------------------------------------------------------------
// FP16 tensor-core GEMM: 128x128 blocktile, BK=32, 3-stage cp.async ring,
// ldmatrix fragment loads. 256 threads = 8 warps (4m x 2n); warp tile 32x64;
// mma.m16n8k16.f16 with fp32 accumulate.
// SPLIT=false: C = fp32 [M,N] standard store (Cf, row stride N).
// SPLIT=true (GEMM1, N=1536): bn<6 -> xc fp32 [M,768]; bn>=6 -> silu+fp16
//   to zs [M,768].
// ---------------------------------------------------------------------------
#define BM 128
#define BN 128
#define BKT 32
#define STAGES 3
#define AH_STRIDE 40                        // 32 + 8 pad halfs (80B rows)
#define BH_STRIDE 136                       // 128 + 8 pad halfs (272B rows)
#define A_STAGE_H (BM * AH_STRIDE)          // 5120 halfs = 10240 B
#define B_STAGE_H (BKT * BH_STRIDE)         // 4352 halfs = 8704 B
#define GEMM_SMEM_BYTES (STAGES * (A_STAGE_H + B_STAGE_H) * 2)  // 56832

__device__ __forceinline__ void mma_fp16(float* d, const uint32_t* a, const uint32_t* b) {
    asm volatile(
        "mma.sync.aligned.m16n8k16.row.col.f32.f16.f16.f32 "
        "{%0,%1,%2,%3}, {%4,%5,%6,%7}, {%8,%9}, {%0,%1,%2,%3};\n"
        : "+f"(d[0]), "+f"(d[1]), "+f"(d[2]), "+f"(d[3])
        : "r"(a[0]), "r"(a[1]), "r"(a[2]), "r"(a[3]), "r"(b[0]), "r"(b[1]));
}

__device__ __forceinline__ void ldsm_x4(uint32_t* r, uint32_t addr) {
    asm volatile("ldmatrix.sync.aligned.m8n8.x4.shared.b16 {%0,%1,%2,%3}, [%4];"
                 : "=r"(r[0]), "=r"(r[1]), "=r"(r[2]), "=r"(r[3]) : "r"(addr));
}
__device__ __forceinline__ void ldsm_x4_t(uint32_t* r, uint32_t addr) {
    asm volatile("ldmatrix.sync.aligned.m8n8.x4.trans.shared.b16 {%0,%1,%2,%3}, [%4];"
                 : "=r"(r[0]), "=r"(r[1]), "=r"(r[2]), "=r"(r[3]) : "r"(addr));
}

__device__ __forceinline__ void cpa16(void* dst, const void* src) {
    unsigned d = (unsigned)__cvta_generic_to_shared(dst);
    asm volatile("cp.async.cg.shared.global [%0], [%1], 16;" :: "r"(d), "l"(src) : "memory");
}

template<bool SPLIT>
__global__ __launch_bounds__(256, 2) void gemm_fp16_kernel(
    const __half* __restrict__ A, const __half* __restrict__ Bh,
    float* __restrict__ Cf, __half* __restrict__ Ch,
    int M, int N, int K)
{
    extern __shared__ char smem[];
    __half* Asm = (__half*)smem;                            // [STAGES][BM][AH_STRIDE]
    __half* Bsm = (__half*)(smem + STAGES * A_STAGE_H * 2); // [STAGES][BKT][BH_STRIDE]

    const int tid  = threadIdx.x;
    const int lane = tid & 31;
    const int wid  = tid >> 5;
    const int wm   = wid >> 1;   // 0..3 -> m offset 32*wm
    const int wn   = wid & 1;    // 0..1 -> n offset 64*wn
    const int bm   = blockIdx.y;
    const int bn   = blockIdx.x;

    const __half* Ab = A + (size_t)bm * BM * K;
    const __half* Bb = Bh + (size_t)bn * BN;

    float acc[2][8][4];
    #pragma unroll
    for (int mi = 0; mi < 2; mi++)
        #pragma unroll
        for (int ni = 0; ni < 8; ni++)
            #pragma unroll
            for (int q = 0; q < 4; q++) acc[mi][ni][q] = 0.0f;

    const int NT = K / BKT;   // 24

    auto load_stage = [&](int kt, int st) {
        __half* As = Asm + st * A_STAGE_H;
        __half* Bs = Bsm + st * B_STAGE_H;
        const int k0 = kt * BKT;
        #pragma unroll
        for (int i = 0; i < 2; i++) {
            const int idx = tid + i * 256;
            const int r = idx >> 2, c8 = (idx & 3) << 3;
            cpa16(&As[r * AH_STRIDE + c8], Ab + (size_t)r * K + k0 + c8);
        }
        #pragma unroll
        for (int i = 0; i < 2; i++) {
            const int idx = tid + i * 256;
            const int r = idx >> 4, c8 = (idx & 15) << 3;
            cpa16(&Bs[r * BH_STRIDE + c8], Bb + (size_t)(k0 + r) * N + c8);
        }
        asm volatile("cp.async.commit_group;" ::: "memory");
    };

    const uint32_t asm_u32 = (uint32_t)__cvta_generic_to_shared(Asm);
    const uint32_t bsm_u32 = (uint32_t)__cvta_generic_to_shared(Bsm);
    const uint32_t a_lane = ((wm * 32 + (lane & 15)) * AH_STRIDE + (lane >> 4) * 8) * 2;
    const uint32_t b_lane = (((((lane >> 3) & 1) * 8) + (lane & 7)) * BH_STRIDE
                             + wn * 64 + (lane >> 4) * 8) * 2;

    load_stage(0, 0);
    load_stage(1, 1);

    for (int kt = 0; kt < NT; kt++) {
        if (kt + 2 < NT) {
            asm volatile("cp.async.wait_group 1;" ::: "memory");
        } else {
            asm volatile("cp.async.wait_group 0;" ::: "memory");
        }
        __syncthreads();

        if (kt + 2 < NT) load_stage(kt + 2, (kt + 2) % STAGES);

        const int st = kt % STAGES;
        const uint32_t a_st = asm_u32 + st * A_STAGE_H * 2 + a_lane;
        const uint32_t b_st = bsm_u32 + st * B_STAGE_H * 2 + b_lane;

        #pragma unroll
        for (int ks2 = 0; ks2 < 2; ks2++) {
            uint32_t afr[2][4];
            const uint32_t aa = a_st + ks2 * 32;
            ldsm_x4(afr[0], aa);
            ldsm_x4(afr[1], aa + 16 * AH_STRIDE * 2);

            uint32_t bfr[8][2];
            #pragma unroll
            for (int ni2 = 0; ni2 < 4; ni2++) {
                uint32_t r[4];
                ldsm_x4_t(r, b_st + ks2 * 16 * BH_STRIDE * 2 + ni2 * 32);
                bfr[2 * ni2][0] = r[0]; bfr[2 * ni2][1] = r[1];
                bfr[2 * ni2 + 1][0] = r[2]; bfr[2 * ni2 + 1][1] = r[3];
            }
            #pragma unroll
            for (int mi = 0; mi < 2; mi++)
                #pragma unroll
                for (int ni = 0; ni < 8; ni++)
                    mma_fp16(acc[mi][ni], afr[mi], bfr[ni]);
        }
    }

    if (!SPLIT) {
        float* Cb = Cf + (size_t)bm * BM * N + (size_t)bn * BN;
        #pragma unroll
        for (int mi = 0; mi < 2; mi++) {
            #pragma unroll
            for (int ni = 0; ni < 8; ni++) {
                const int r = wm * 32 + mi * 16 + (lane >> 2);
                const int c = wn * 64 + ni * 8 + ((lane & 3) << 1);
                *(float2*)&Cb[(size_t)r * N + c] =
                    make_float2(acc[mi][ni][0], acc[mi][ni][1]);
                *(float2*)&Cb[(size_t)(r + 8) * N + c] =
                    make_float2(acc[mi][ni][2], acc[mi][ni][3]);
            }
        }
    } else if (bn < 6) {
        // xc half: raw fp32 store, row stride 768
        float* Cb = Cf + (size_t)bm * BM * D_INNER + (size_t)bn * BN;
        #pragma unroll
        for (int mi = 0; mi < 2; mi++) {
            #pragma unroll
            for (int ni = 0; ni < 8; ni++) {
                const int r = wm * 32 + mi * 16 + (lane >> 2);
                const int c = wn * 64 + ni * 8 + ((lane & 3) << 1);
                *(float2*)&Cb[(size_t)r * D_INNER + c] =
                    make_float2(acc[mi][ni][0], acc[mi][ni][1]);
                *(float2*)&Cb[(size_t)(r + 8) * D_INNER + c] =
                    make_float2(acc[mi][ni][2], acc[mi][ni][3]);
            }
        }
    } else {
        // z half: silu + fp16 store, row stride 768
        __half* Zb = Ch + (size_t)bm * BM * D_INNER + (size_t)(bn - 6) * BN;
        #pragma unroll
        for (int mi = 0; mi < 2; mi++) {
            #pragma unroll
            for (int ni = 0; ni < 8; ni++) {
                const int r = wm * 32 + mi * 16 + (lane >> 2);
                const int c = wn * 64 + ni * 8 + ((lane & 3) << 1);
                __half2 h0 = __floats2half2_rn(silu_f(acc[mi][ni][0]),
                                               silu_f(acc[mi][ni][1]));
                __half2 h1 = __floats2half2_rn(silu_f(acc[mi][ni][2]),
                                               silu_f(acc[mi][ni][3]));
                *(uint32_t*)&Zb[(size_t)r * D_INNER + c] = *(uint32_t*)&h0;
                *(uint32_t*)&Zb[(size_t)(r + 8) * D_INNER + c] = *(uint32_t*)&h1;
            }
        }
    }
}

// ---------------------------------------------------------------------------
// Pass A: per-chunk sums of u = silu(conv3(xc)+bias). 4 channels per thread.
// xc is [B*SEQ][768] fp32.
// ---------------------------------------------------------------------------
__global__ __launch_bounds__(192) void scan_partial_kernel(
    const float* __restrict__ xc,
    const float* __restrict__ convw, const float* __restrict__ convb,
    float* __restrict__ csum)
{
    const int tq = threadIdx.x;
    const int chunk = blockIdx.x;
    const int b = blockIdx.y;
    const int t0 = chunk * CHUNK;
    const int c0 = tq * 4;

    float w0[4], w1[4], w2[4], cb[4];
    #pragma unroll
    for (int j = 0; j < 4; j++) {
        w0[j] = convw[(c0 + j) * 3 + 0];
        w1[j] = convw[(c0 + j) * 3 + 1];
        w2[j] = convw[(c0 + j) * 3 + 2];
        cb[j] = convb[c0 + j];
    }

    const float* p = xc + ((size_t)b * SEQ + t0) * D_INNER + c0;

    float4 xm2 = make_float4(0, 0, 0, 0), xm1 = make_float4(0, 0, 0, 0);
    if (t0 >= 2) {
        xm2 = *(const float4*)(p - 2 * D_INNER);
        xm1 = *(const float4*)(p - 1 * D_INNER);
    }

    float s[4] = {0, 0, 0, 0};
    #pragma unroll 8
    for (int t = 0; t < CHUNK; t++) {
        float4 x0 = *(const float4*)(p + (size_t)t * D_INNER);
        float m2[4] = {xm2.x, xm2.y, xm2.z, xm2.w};
        float m1[4] = {xm1.x, xm1.y, xm1.z, xm1.w};
        float cc[4] = {x0.x, x0.y, x0.z, x0.w};
        #pragma unroll
        for (int j = 0; j < 4; j++) {
            float v = fmaf(w0[j], m2[j], fmaf(w1[j], m1[j], fmaf(w2[j], cc[j], cb[j])));
            s[j] += silu_f(v);
        }
        xm2 = xm1; xm1 = x0;
    }
    *(float4*)&csum[((size_t)b * NCHUNK + chunk) * D_INNER + c0] =
        make_float4(s[0], s[1], s[2], s[3]);
}

// ---------------------------------------------------------------------------
// Pass B: block-parallel exclusive scan over NCHUNK chunk sums.
// ---------------------------------------------------------------------------
__global__ __launch_bounds__(NCHUNK) void scan_offsets_kernel(float* __restrict__ csum)
{
    __shared__ float4 sh[NCHUNK];
    const int k = threadIdx.x;
    const int c0 = blockIdx.x * 4;
    const int b = blockIdx.y;

    float4* ptr = (float4*)&csum[((size_t)b * NCHUNK + k) * D_INNER + c0];
    float4 v = *ptr;
    sh[k] = v;
    __syncthreads();

    #pragma unroll
    for (int off = 1; off < NCHUNK; off <<= 1) {
        float4 t = make_float4(0, 0, 0, 0);
        const bool has = (k >= off);
        if (has) t = sh[k - off];
        __syncthreads();
        if (has) {
            v.x += t.x; v.y += t.y; v.z += t.z; v.w += t.w;
            sh[k] = v;
        }
        __syncthreads();
    }
    float4 ex = (k > 0) ? sh[k - 1] : make_float4(0, 0, 0, 0);
    *ptr = ex;
}

// ---------------------------------------------------------------------------
// Pass C: recompute u, y = cum*BC + u*D, times silu(z) (fp16); write fp16 yz.
// ---------------------------------------------------------------------------
__global__ __launch_bounds__(192) void scan_apply_kernel(
    const float* __restrict__ xc,
    const __half* __restrict__ zs,
    const float* __restrict__ convw, const float* __restrict__ convb,
    const float* __restrict__ Bm, const float* __restrict__ Cm,
    const float* __restrict__ Dv,
    const float* __restrict__ csum,
    __half* __restrict__ yz)
{
    const int tq = threadIdx.x;
    const int chunk = blockIdx.x;
    const int b = blockIdx.y;
    const int t0 = chunk * CHUNK;
    const int c0 = tq * 4;

    float w0[4], w1[4], w2[4], cb[4], bc[4], dd[4];
    #pragma unroll
    for (int j = 0; j < 4; j++) {
        w0[j] = convw[(c0 + j) * 3 + 0];
        w1[j] = convw[(c0 + j) * 3 + 1];
        w2[j] = convw[(c0 + j) * 3 + 2];
        cb[j] = convb[c0 + j];
        float acc = 0.0f;
        #pragma unroll
        for (int s = 0; s < D_STATE; s++)
            acc = fmaf(Bm[(c0 + j) * D_STATE + s], Cm[(c0 + j) * D_STATE + s], acc);
        bc[j] = acc;
        dd[j] = Dv[c0 + j];
    }

    const float*  p  = xc + ((size_t)b * SEQ + t0) * D_INNER + c0;
    const __half* zp = zs + ((size_t)b * SEQ + t0) * D_INNER + c0;
    __half* q = yz + ((size_t)b * SEQ + t0) * D_INNER + c0;

    float4 xm2 = make_float4(0, 0, 0, 0), xm1 = make_float4(0, 0, 0, 0);
    if (t0 >= 2) {
        xm2 = *(const float4*)(p - 2 * D_INNER);
        xm1 = *(const float4*)(p - 1 * D_INNER);
    }

    float4 runv = *(const float4*)&csum[((size_t)b * NCHUNK + chunk) * D_INNER + c0];
    float run[4] = {runv.x, runv.y, runv.z, runv.w};

    #pragma unroll 8
    for (int t = 0; t < CHUNK; t++) {
        float4 x0 = *(const float4*)(p + (size_t)t * D_INNER);
        uint2 zraw = *(const uint2*)(zp + (size_t)t * D_INNER);
        __half2 zh0 = *(__half2*)&zraw.x;
        __half2 zh1 = *(__half2*)&zraw.y;
        float2 zf0 = __half22float2(zh0);
        float2 zf1 = __half22float2(zh1);
        float m2[4] = {xm2.x, xm2.y, xm2.z, xm2.w};
        float m1[4] = {xm1.x, xm1.y, xm1.z, xm1.w};
        float cc[4] = {x0.x, x0.y, x0.z, x0.w};
        float zv[4] = {zf0.x, zf0.y, zf1.x, zf1.y};
        float o[4];
        #pragma unroll
        for (int j = 0; j < 4; j++) {
            float v = fmaf(w0[j], m2[j], fmaf(w1[j], m1[j], fmaf(w2[j], cc[j], cb[j])));
            float u = silu_f(v);
            run[j] += u;
            float y = fmaf(run[j], bc[j], u * dd[j]);
            o[j] = y * zv[j];
        }
        __half2 h01 = __floats2half2_rn(o[0], o[1]);
        __half2 h23 = __floats2half2_rn(o[2], o[3]);
        *(uint2*)(q + (size_t)t * D_INNER) =
            make_uint2(*(uint32_t*)&h01, *(uint32_t*)&h23);
        xm2 = xm1; xm1 = x0;
    }
}

// ---------------------------------------------------------------------------
// Launch
// ---------------------------------------------------------------------------
extern "C" void kernel_launch(void* const* d_in, const int* in_sizes, int n_in,
                              void* d_out, int out_size)
{
    const float* x      = (const float*)d_in[0];
    const float* W_in   = (const float*)d_in[1];
    const float* conv_w = (const float*)d_in[2];
    const float* conv_b = (const float*)d_in[3];
    const float* Bm     = (const float*)d_in[4];
    const float* Cm     = (const float*)d_in[5];
    const float* Dv     = (const float*)d_in[6];
    const float* W_out  = (const float*)d_in[7];
    float* out = (float*)d_out;

    __half* xh;  cudaGetSymbolAddress((void**)&xh, g_Xh);
    float*  xc;  cudaGetSymbolAddress((void**)&xc, g_XC);
    __half* zsp; cudaGetSymbolAddress((void**)&zsp, g_ZS);
    __half* yzh; cudaGetSymbolAddress((void**)&yzh, g_YZh);
    __half* wh;  cudaGetSymbolAddress((void**)&wh, g_Wh);
    float*  cs;  cudaGetSymbolAddress((void**)&cs, g_CS);

    __half* wh_in  = wh;                             // [768][1536]
    __half* wh_out = wh + (size_t)KDIM * N_IN;       // [768][768]

    static bool attr_done = false;
    if (!attr_done) {
        cudaFuncSetAttribute(gemm_fp16_kernel<true>,
                             cudaFuncAttributeMaxDynamicSharedMemorySize, GEMM_SMEM_BYTES);
        cudaFuncSetAttribute(gemm_fp16_kernel<false>,
                             cudaFuncAttributeMaxDynamicSharedMemorySize, GEMM_SMEM_BYTES);
        attr_done = true;
    }

    // Preprocessing: x and weights -> fp16
    {
        int n4 = (M_TOT * D_MODEL) / 4;
        convert_h_kernel<<<(n4 + 255) / 256, 256>>>(x, xh, n4);
        n4 = (KDIM * N_IN) / 4;
        convert_h_kernel<<<(n4 + 255) / 256, 256>>>(W_in, wh_in, n4);
        n4 = (KDIM * D_MODEL) / 4;
        convert_h_kernel<<<(n4 + 255) / 256, 256>>>(W_out, wh_out, n4);
    }

    // GEMM1 (split epilogue): xc fp32 + zs=silu(z) fp16
    {
        dim3 grid(N_IN / BN, M_TOT / BM);
        gemm_fp16_kernel<true><<<grid, 256, GEMM_SMEM_BYTES>>>(
            xh, wh_in, xc, zsp, M_TOT, N_IN, KDIM);
    }
    // Scan pipeline
    {
        dim3 grid(NCHUNK, BATCH);
        scan_partial_kernel<<<grid, 192>>>(xc, conv_w, conv_b, cs);
        scan_offsets_kernel<<<dim3(D_INNER / 4, BATCH), NCHUNK>>>(cs);
        scan_apply_kernel<<<grid, 192>>>(xc, zsp, conv_w, conv_b, Bm, Cm, Dv, cs, yzh);
    }
    // GEMM2: out = yzh @ W_out  [32768,768] x [768,768]
    {
        dim3 grid(D_MODEL / BN, M_TOT / BM);
        gemm_fp16_kernel<false><<<grid, 256, GEMM_SMEM_BYTES>>>(
            yzh, wh_out, out, nullptr, M_TOT, D_MODEL, KDIM);
    }
}

// round 16
// speedup vs baseline: 1.0505x; 1.0239x over previous
#include <cuda_runtime.h>
#include <cuda_fp16.h>
#include <cstdint>

// Problem constants
#define D_MODEL 768
#define D_INNER 768
#define D_STATE 8
#define BATCH   4
#define SEQ     8192
#define M_TOT   (BATCH * SEQ)        // 32768
#define N_IN    (2 * D_INNER)        // 1536
#define KDIM    768
#define CHUNK   32
#define NCHUNK  (SEQ / CHUNK)        // 256

// Scratch (static __device__ arrays per allocation rules)
__device__ __half g_Xh[(size_t)M_TOT * D_MODEL];         // fp16 x
__device__ __half g_XC[(size_t)M_TOT * D_INNER];         // xc fp16 (pre-conv)
__device__ __half g_ZS[(size_t)M_TOT * D_INNER];         // silu(z) fp16
__device__ __half g_YZh[(size_t)M_TOT * D_INNER];        // fp16 y*silu(z)
__device__ __half g_Wh[(size_t)KDIM * N_IN + (size_t)KDIM * D_MODEL]; // fp16 W_in | W_out
__device__ float  g_CS[(size_t)BATCH * NCHUNK * D_INNER]; // chunk sums / offsets

// ---------------------------------------------------------------------------
// silu helper
// ---------------------------------------------------------------------------
__device__ __forceinline__ float silu_f(float v) {
    return v / (1.0f + __expf(-v));
}

// ---------------------------------------------------------------------------
// fp32 -> fp16 conversion (used for x and both weights)
// ---------------------------------------------------------------------------
__global__ __launch_bounds__(256) void convert_h_kernel(
    const float* __restrict__ in, __half* __restrict__ out, int n4)
{
    int i = blockIdx.x * blockDim.x + threadIdx.x;
    if (i >= n4) return;
    float4 v = ((const float4*)in)[i];
    __half2 h0 = __floats2half2_rn(v.x, v.y);
    __half2 h1 = __floats2half2_rn(v.z, v.w);
    ((uint2*)out)[i] = make_uint2(*(uint32_t*)&h0, *(uint32_t*)&h1);
}

// ---------------------------------------------------------------------------
// FP16 tensor-core GEMM: 128x128 blocktile, BK=32, 3-stage cp.async ring,
// ldmatrix fragment loads. 256 threads = 8 warps (4m x 2n); warp tile 32x64;
// mma.m16n8k16.f16 with fp32 accumulate.
// SPLIT=false: C = fp32 [M,N] standard store (Cf, row stride N).
// SPLIT=true (GEMM1, N=1536): bn<6 -> xc fp16 [M,768]; bn>=6 -> silu+fp16
//   to zs [M,768].
// ---------------------------------------------------------------------------
#define BM 128
#define BN 128
#define BKT 32
#define STAGES 3
#define AH_STRIDE 40                        // 32 + 8 pad halfs (80B rows)
#define BH_STRIDE 136                       // 128 + 8 pad halfs (272B rows)
#define A_STAGE_H (BM * AH_STRIDE)          // 5120 halfs = 10240 B
#define B_STAGE_H (BKT * BH_STRIDE)         // 4352 halfs = 8704 B
#define GEMM_SMEM_BYTES (STAGES * (A_STAGE_H + B_STAGE_H) * 2)  // 56832

__device__ __forceinline__ void mma_fp16(float* d, const uint32_t* a, const uint32_t* b) {
    asm volatile(
        "mma.sync.aligned.m16n8k16.row.col.f32.f16.f16.f32 "
        "{%0,%1,%2,%3}, {%4,%5,%6,%7}, {%8,%9}, {%0,%1,%2,%3};\n"
        : "+f"(d[0]), "+f"(d[1]), "+f"(d[2]), "+f"(d[3])
        : "r"(a[0]), "r"(a[1]), "r"(a[2]), "r"(a[3]), "r"(b[0]), "r"(b[1]));
}

__device__ __forceinline__ void ldsm_x4(uint32_t* r, uint32_t addr) {
    asm volatile("ldmatrix.sync.aligned.m8n8.x4.shared.b16 {%0,%1,%2,%3}, [%4];"
                 : "=r"(r[0]), "=r"(r[1]), "=r"(r[2]), "=r"(r[3]) : "r"(addr));
}
__device__ __forceinline__ void ldsm_x4_t(uint32_t* r, uint32_t addr) {
    asm volatile("ldmatrix.sync.aligned.m8n8.x4.trans.shared.b16 {%0,%1,%2,%3}, [%4];"
                 : "=r"(r[0]), "=r"(r[1]), "=r"(r[2]), "=r"(r[3]) : "r"(addr));
}

__device__ __forceinline__ void cpa16(void* dst, const void* src) {
    unsigned d = (unsigned)__cvta_generic_to_shared(dst);
    asm volatile("cp.async.cg.shared.global [%0], [%1], 16;" :: "r"(d), "l"(src) : "memory");
}

template<bool SPLIT>
__global__ __launch_bounds__(256, 2) void gemm_fp16_kernel(
    const __half* __restrict__ A, const __half* __restrict__ Bh,
    float* __restrict__ Cf, __half* __restrict__ Cxc, __half* __restrict__ Czs,
    int M, int N, int K)
{
    extern __shared__ char smem[];
    __half* Asm = (__half*)smem;                            // [STAGES][BM][AH_STRIDE]
    __half* Bsm = (__half*)(smem + STAGES * A_STAGE_H * 2); // [STAGES][BKT][BH_STRIDE]

    const int tid  = threadIdx.x;
    const int lane = tid & 31;
    const int wid  = tid >> 5;
    const int wm   = wid >> 1;   // 0..3 -> m offset 32*wm
    const int wn   = wid & 1;    // 0..1 -> n offset 64*wn
    const int bm   = blockIdx.y;
    const int bn   = blockIdx.x;

    const __half* Ab = A + (size_t)bm * BM * K;
    const __half* Bb = Bh + (size_t)bn * BN;

    float acc[2][8][4];
    #pragma unroll
    for (int mi = 0; mi < 2; mi++)
        #pragma unroll
        for (int ni = 0; ni < 8; ni++)
            #pragma unroll
            for (int q = 0; q < 4; q++) acc[mi][ni][q] = 0.0f;

    const int NT = K / BKT;   // 24

    auto load_stage = [&](int kt, int st) {
        __half* As = Asm + st * A_STAGE_H;
        __half* Bs = Bsm + st * B_STAGE_H;
        const int k0 = kt * BKT;
        #pragma unroll
        for (int i = 0; i < 2; i++) {
            const int idx = tid + i * 256;
            const int r = idx >> 2, c8 = (idx & 3) << 3;
            cpa16(&As[r * AH_STRIDE + c8], Ab + (size_t)r * K + k0 + c8);
        }
        #pragma unroll
        for (int i = 0; i < 2; i++) {
            const int idx = tid + i * 256;
            const int r = idx >> 4, c8 = (idx & 15) << 3;
            cpa16(&Bs[r * BH_STRIDE + c8], Bb + (size_t)(k0 + r) * N + c8);
        }
        asm volatile("cp.async.commit_group;" ::: "memory");
    };

    const uint32_t asm_u32 = (uint32_t)__cvta_generic_to_shared(Asm);
    const uint32_t bsm_u32 = (uint32_t)__cvta_generic_to_shared(Bsm);
    const uint32_t a_lane = ((wm * 32 + (lane & 15)) * AH_STRIDE + (lane >> 4) * 8) * 2;
    const uint32_t b_lane = (((((lane >> 3) & 1) * 8) + (lane & 7)) * BH_STRIDE
                             + wn * 64 + (lane >> 4) * 8) * 2;

    load_stage(0, 0);
    load_stage(1, 1);

    for (int kt = 0; kt < NT; kt++) {
        if (kt + 2 < NT) {
            asm volatile("cp.async.wait_group 1;" ::: "memory");
        } else {
            asm volatile("cp.async.wait_group 0;" ::: "memory");
        }
        __syncthreads();

        if (kt + 2 < NT) load_stage(kt + 2, (kt + 2) % STAGES);

        const int st = kt % STAGES;
        const uint32_t a_st = asm_u32 + st * A_STAGE_H * 2 + a_lane;
        const uint32_t b_st = bsm_u32 + st * B_STAGE_H * 2 + b_lane;

        #pragma unroll
        for (int ks2 = 0; ks2 < 2; ks2++) {
            uint32_t afr[2][4];
            const uint32_t aa = a_st + ks2 * 32;
            ldsm_x4(afr[0], aa);
            ldsm_x4(afr[1], aa + 16 * AH_STRIDE * 2);

            uint32_t bfr[8][2];
            #pragma unroll
            for (int ni2 = 0; ni2 < 4; ni2++) {
                uint32_t r[4];
                ldsm_x4_t(r, b_st + ks2 * 16 * BH_STRIDE * 2 + ni2 * 32);
                bfr[2 * ni2][0] = r[0]; bfr[2 * ni2][1] = r[1];
                bfr[2 * ni2 + 1][0] = r[2]; bfr[2 * ni2 + 1][1] = r[3];
            }
            #pragma unroll
            for (int mi = 0; mi < 2; mi++)
                #pragma unroll
                for (int ni = 0; ni < 8; ni++)
                    mma_fp16(acc[mi][ni], afr[mi], bfr[ni]);
        }
    }

    if (!SPLIT) {
        float* Cb = Cf + (size_t)bm * BM * N + (size_t)bn * BN;
        #pragma unroll
        for (int mi = 0; mi < 2; mi++) {
            #pragma unroll
            for (int ni = 0; ni < 8; ni++) {
                const int r = wm * 32 + mi * 16 + (lane >> 2);
                const int c = wn * 64 + ni * 8 + ((lane & 3) << 1);
                *(float2*)&Cb[(size_t)r * N + c] =
                    make_float2(acc[mi][ni][0], acc[mi][ni][1]);
                *(float2*)&Cb[(size_t)(r + 8) * N + c] =
                    make_float2(acc[mi][ni][2], acc[mi][ni][3]);
            }
        }
    } else if (bn < 6) {
        // xc half: raw fp16 store, row stride 768
        __half* Xb = Cxc + (size_t)bm * BM * D_INNER + (size_t)bn * BN;
        #pragma unroll
        for (int mi = 0; mi < 2; mi++) {
            #pragma unroll
            for (int ni = 0; ni < 8; ni++) {
                const int r = wm * 32 + mi * 16 + (lane >> 2);
                const int c = wn * 64 + ni * 8 + ((lane & 3) << 1);
                __half2 h0 = __floats2half2_rn(acc[mi][ni][0], acc[mi][ni][1]);
                __half2 h1 = __floats2half2_rn(acc[mi][ni][2], acc[mi][ni][3]);
                *(uint32_t*)&Xb[(size_t)r * D_INNER + c] = *(uint32_t*)&h0;
                *(uint32_t*)&Xb[(size_t)(r + 8) * D_INNER + c] = *(uint32_t*)&h1;
            }
        }
    } else {
        // z half: silu + fp16 store, row stride 768
        __half* Zb = Czs + (size_t)bm * BM * D_INNER + (size_t)(bn - 6) * BN;
        #pragma unroll
        for (int mi = 0; mi < 2; mi++) {
            #pragma unroll
            for (int ni = 0; ni < 8; ni++) {
                const int r = wm * 32 + mi * 16 + (lane >> 2);
                const int c = wn * 64 + ni * 8 + ((lane & 3) << 1);
                __half2 h0 = __floats2half2_rn(silu_f(acc[mi][ni][0]),
                                               silu_f(acc[mi][ni][1]));
                __half2 h1 = __floats2half2_rn(silu_f(acc[mi][ni][2]),
                                               silu_f(acc[mi][ni][3]));
                *(uint32_t*)&Zb[(size_t)r * D_INNER + c] = *(uint32_t*)&h0;
                *(uint32_t*)&Zb[(size_t)(r + 8) * D_INNER + c] = *(uint32_t*)&h1;
            }
        }
    }
}

// ---------------------------------------------------------------------------
// fp16 quad load helper: 4 consecutive halfs -> float[4]
// ---------------------------------------------------------------------------
__device__ __forceinline__ void ld_h4(const __half* p, float* f) {
    uint2 raw = *(const uint2*)p;
    float2 a = __half22float2(*(__half2*)&raw.x);
    float2 b = __half22float2(*(__half2*)&raw.y);
    f[0] = a.x; f[1] = a.y; f[2] = b.x; f[3] = b.y;
}

// ---------------------------------------------------------------------------
// Pass A: per-chunk sums of u = silu(conv3(xc)+bias). 4 channels per thread.
// xc is [B*SEQ][768] fp16.
// ---------------------------------------------------------------------------
__global__ __launch_bounds__(192) void scan_partial_kernel(
    const __half* __restrict__ xc,
    const float* __restrict__ convw, const float* __restrict__ convb,
    float* __restrict__ csum)
{
    const int tq = threadIdx.x;
    const int chunk = blockIdx.x;
    const int b = blockIdx.y;
    const int t0 = chunk * CHUNK;
    const int c0 = tq * 4;

    float w0[4], w1[4], w2[4], cb[4];
    #pragma unroll
    for (int j = 0; j < 4; j++) {
        w0[j] = convw[(c0 + j) * 3 + 0];
        w1[j] = convw[(c0 + j) * 3 + 1];
        w2[j] = convw[(c0 + j) * 3 + 2];
        cb[j] = convb[c0 + j];
    }

    const __half* p = xc + ((size_t)b * SEQ + t0) * D_INNER + c0;

    float m2[4] = {0, 0, 0, 0}, m1[4] = {0, 0, 0, 0};
    if (t0 >= 2) {
        ld_h4(p - 2 * D_INNER, m2);
        ld_h4(p - 1 * D_INNER, m1);
    }

    float s[4] = {0, 0, 0, 0};
    #pragma unroll 8
    for (int t = 0; t < CHUNK; t++) {
        float cc[4];
        ld_h4(p + (size_t)t * D_INNER, cc);
        #pragma unroll
        for (int j = 0; j < 4; j++) {
            float v = fmaf(w0[j], m2[j], fmaf(w1[j], m1[j], fmaf(w2[j], cc[j], cb[j])));
            s[j] += silu_f(v);
            m2[j] = m1[j]; m1[j] = cc[j];
        }
    }
    *(float4*)&csum[((size_t)b * NCHUNK + chunk) * D_INNER + c0] =
        make_float4(s[0], s[1], s[2], s[3]);
}

// ---------------------------------------------------------------------------
// Pass B: block-parallel exclusive scan over NCHUNK chunk sums.
// ---------------------------------------------------------------------------
__global__ __launch_bounds__(NCHUNK) void scan_offsets_kernel(float* __restrict__ csum)
{
    __shared__ float4 sh[NCHUNK];
    const int k = threadIdx.x;
    const int c0 = blockIdx.x * 4;
    const int b = blockIdx.y;

    float4* ptr = (float4*)&csum[((size_t)b * NCHUNK + k) * D_INNER + c0];
    float4 v = *ptr;
    sh[k] = v;
    __syncthreads();

    #pragma unroll
    for (int off = 1; off < NCHUNK; off <<= 1) {
        float4 t = make_float4(0, 0, 0, 0);
        const bool has = (k >= off);
        if (has) t = sh[k - off];
        __syncthreads();
        if (has) {
            v.x += t.x; v.y += t.y; v.z += t.z; v.w += t.w;
            sh[k] = v;
        }
        __syncthreads();
    }
    float4 ex = (k > 0) ? sh[k - 1] : make_float4(0, 0, 0, 0);
    *ptr = ex;
}

// ---------------------------------------------------------------------------
// Pass C: recompute u, y = cum*BC + u*D, times silu(z) (fp16); write fp16 yz.
// ---------------------------------------------------------------------------
__global__ __launch_bounds__(192) void scan_apply_kernel(
    const __half* __restrict__ xc,
    const __half* __restrict__ zs,
    const float* __restrict__ convw, const float* __restrict__ convb,
    const float* __restrict__ Bm, const float* __restrict__ Cm,
    const float* __restrict__ Dv,
    const float* __restrict__ csum,
    __half* __restrict__ yz)
{
    const int tq = threadIdx.x;
    const int chunk = blockIdx.x;
    const int b = blockIdx.y;
    const int t0 = chunk * CHUNK;
    const int c0 = tq * 4;

    float w0[4], w1[4], w2[4], cb[4], bc[4], dd[4];
    #pragma unroll
    for (int j = 0; j < 4; j++) {
        w0[j] = convw[(c0 + j) * 3 + 0];
        w1[j] = convw[(c0 + j) * 3 + 1];
        w2[j] = convw[(c0 + j) * 3 + 2];
        cb[j] = convb[c0 + j];
        float acc = 0.0f;
        #pragma unroll
        for (int s = 0; s < D_STATE; s++)
            acc = fmaf(Bm[(c0 + j) * D_STATE + s], Cm[(c0 + j) * D_STATE + s], acc);
        bc[j] = acc;
        dd[j] = Dv[c0 + j];
    }

    const __half* p  = xc + ((size_t)b * SEQ + t0) * D_INNER + c0;
    const __half* zp = zs + ((size_t)b * SEQ + t0) * D_INNER + c0;
    __half* q = yz + ((size_t)b * SEQ + t0) * D_INNER + c0;

    float m2[4] = {0, 0, 0, 0}, m1[4] = {0, 0, 0, 0};
    if (t0 >= 2) {
        ld_h4(p - 2 * D_INNER, m2);
        ld_h4(p - 1 * D_INNER, m1);
    }

    float4 runv = *(const float4*)&csum[((size_t)b * NCHUNK + chunk) * D_INNER + c0];
    float run[4] = {runv.x, runv.y, runv.z, runv.w};

    #pragma unroll 8
    for (int t = 0; t < CHUNK; t++) {
        float cc[4], zv[4];
        ld_h4(p + (size_t)t * D_INNER, cc);
        ld_h4(zp + (size_t)t * D_INNER, zv);
        float o[4];
        #pragma unroll
        for (int j = 0; j < 4; j++) {
            float v = fmaf(w0[j], m2[j], fmaf(w1[j], m1[j], fmaf(w2[j], cc[j], cb[j])));
            float u = silu_f(v);
            run[j] += u;
            float y = fmaf(run[j], bc[j], u * dd[j]);
            o[j] = y * zv[j];
            m2[j] = m1[j]; m1[j] = cc[j];
        }
        __half2 h01 = __floats2half2_rn(o[0], o[1]);
        __half2 h23 = __floats2half2_rn(o[2], o[3]);
        *(uint2*)(q + (size_t)t * D_INNER) =
            make_uint2(*(uint32_t*)&h01, *(uint32_t*)&h23);
    }
}

// ---------------------------------------------------------------------------
// Launch
// ---------------------------------------------------------------------------
extern "C" void kernel_launch(void* const* d_in, const int* in_sizes, int n_in,
                              void* d_out, int out_size)
{
    const float* x      = (const float*)d_in[0];
    const float* W_in   = (const float*)d_in[1];
    const float* conv_w = (const float*)d_in[2];
    const float* conv_b = (const float*)d_in[3];
    const float* Bm     = (const float*)d_in[4];
    const float* Cm     = (const float*)d_in[5];
    const float* Dv     = (const float*)d_in[6];
    const float* W_out  = (const float*)d_in[7];
    float* out = (float*)d_out;

    __half* xh;  cudaGetSymbolAddress((void**)&xh, g_Xh);
    __half* xcp; cudaGetSymbolAddress((void**)&xcp, g_XC);
    __half* zsp; cudaGetSymbolAddress((void**)&zsp, g_ZS);
    __half* yzh; cudaGetSymbolAddress((void**)&yzh, g_YZh);
    __half* wh;  cudaGetSymbolAddress((void**)&wh, g_Wh);
    float*  cs;  cudaGetSymbolAddress((void**)&cs, g_CS);

    __half* wh_in  = wh;                             // [768][1536]
    __half* wh_out = wh + (size_t)KDIM * N_IN;       // [768][768]

    static bool attr_done = false;
    if (!attr_done) {
        cudaFuncSetAttribute(gemm_fp16_kernel<true>,
                             cudaFuncAttributeMaxDynamicSharedMemorySize, GEMM_SMEM_BYTES);
        cudaFuncSetAttribute(gemm_fp16_kernel<false>,
                             cudaFuncAttributeMaxDynamicSharedMemorySize, GEMM_SMEM_BYTES);
        attr_done = true;
    }

    // Preprocessing: x and weights -> fp16
    {
        int n4 = (M_TOT * D_MODEL) / 4;
        convert_h_kernel<<<(n4 + 255) / 256, 256>>>(x, xh, n4);
        n4 = (KDIM * N_IN) / 4;
        convert_h_kernel<<<(n4 + 255) / 256, 256>>>(W_in, wh_in, n4);
        n4 = (KDIM * D_MODEL) / 4;
        convert_h_kernel<<<(n4 + 255) / 256, 256>>>(W_out, wh_out, n4);
    }

    // GEMM1 (split epilogue): xc fp16 + zs=silu(z) fp16
    {
        dim3 grid(N_IN / BN, M_TOT / BM);
        gemm_fp16_kernel<true><<<grid, 256, GEMM_SMEM_BYTES>>>(
            xh, wh_in, nullptr, xcp, zsp, M_TOT, N_IN, KDIM);
    }
    // Scan pipeline
    {
        dim3 grid(NCHUNK, BATCH);
        scan_partial_kernel<<<grid, 192>>>(xcp, conv_w, conv_b, cs);
        scan_offsets_kernel<<<dim3(D_INNER / 4, BATCH), NCHUNK>>>(cs);
        scan_apply_kernel<<<grid, 192>>>(xcp, zsp, conv_w, conv_b, Bm, Cm, Dv, cs, yzh);
    }
    // GEMM2: out = yzh @ W_out  [32768,768] x [768,768]
    {
        dim3 grid(D_MODEL / BN, M_TOT / BM);
        gemm_fp16_kernel<false><<<grid, 256, GEMM_SMEM_BYTES>>>(
            yzh, wh_out, out, nullptr, nullptr, M_TOT, D_MODEL, KDIM);
    }
}